// round 12
// baseline (speedup 1.0000x reference)
#include <cuda_runtime.h>

// Appro_WAConv2d: depthwise 7x7 conv with mantissa-approximation factor.
//   term = x*w*(f1+f2-1)/(f1*f2) = u*w + s*(w/f2),  u = x/f1, s = x - u
// Packed f32x2: smem {u,s} float2, weights {w, w/f2}; one fma.rn.f32x2/tap.
// Round-12: R10 skeleton (half-plane persistent tiles, double-buffered
// A/B/C pipeline) +
//  (a) division-free mantissa split (R11-validated): u = x/f1 is a signed
//      power of two up to O(1e-7); 4 integer ops, no MUFU.RCP -> shorter
//      stage-C critical path and fewer live temporaries.
//  (b) __launch_bounds__(392,4): 41-reg cap -> 4 resident blocks,
//      49 warps/SM (77% occ, was 54%) to cover the 29-cyc LDS latency.

#define B_   4
#define C_   192
#define H_   56
#define W_   56
#define K_   7
#define PAD_ 3
#define HR    28            // output rows per tile (half plane)
#define SMROWS 34           // 28 + 2*3 halo rows
#define SR    64            // smem row stride in float2 (pow2 indexing)
#define NTHR  392
#define CELLS (SMROWS * SR) // 2176
#define NTILES (B_ * C_ * 2)  // 1536
#define NBLK  456           // 152 SMs * 3+ resident blocks, even split

// division-free split: u ~= v/f1 (signed power of 2), s = v - u.
// f1 = mantissa-map(|v|+eps) shares the mantissa of a=|v|+eps, so a/f1 is
// exactly 2^(exp(a) + topbit); dropped eps-scale term is O(1e-7).
__device__ __forceinline__ float2 usplit(float v) {
    float a = fabsf(v) + 1e-7f;
    unsigned ab = __float_as_uint(a);
    unsigned ub = (__float_as_uint(v) & 0x80000000u)
                | ((ab & 0x7F800000u) + ((ab & 0x00400000u) << 1));
    float u = __uint_as_float(ub);
    return make_float2(u, v - u);
}

__device__ __forceinline__ unsigned long long fma2(unsigned long long a,
                                                   unsigned long long b,
                                                   unsigned long long c) {
    unsigned long long d;
    asm("fma.rn.f32x2 %0, %1, %2, %3;" : "=l"(d) : "l"(a), "l"(b), "l"(c));
    return d;
}

__device__ __forceinline__ float pairsum(unsigned long long v) {
    return __uint_as_float((unsigned)v) + __uint_as_float((unsigned)(v >> 32));
}

__global__ __launch_bounds__(NTHR, 4)
void waconv_kernel(const float* __restrict__ x,
                   const float* __restrict__ w,
                   float* __restrict__ out) {
    __shared__ __align__(16) float2 sm[2][CELLS];     // {u, s} interleaved
    __shared__ __align__(16) float2 sw[2][K_ * 8];    // {w, w/f2}, rows of 8

    const int tid = threadIdx.x;
    const int t0 = (int)(((long long)blockIdx.x       * NTILES) / NBLK);
    const int t1 = (int)(((long long)(blockIdx.x + 1) * NTILES) / NBLK);

    const int ty = tid / 28;               // 0..13
    const int tx = tid - ty * 28;          // 0..27
    const int y0 = ty * 2;
    const int x0 = tx * 2;

    // ---- prologue: fill buffer 0 with tile t0 (direct, stalls once) ----
    {
        const int plane = t0 >> 1;
        const int h0 = (t0 & 1) * HR;
        const float* __restrict__ xp = x + (size_t)plane * (H_ * W_);
        if (tid < K_ * 8) {
            int j = tid & 7;
            float2 v2 = make_float2(0.0f, 0.0f);
            if (j < K_) {
                float wv = w[(plane % C_) * (K_ * K_) + (tid >> 3) * K_ + j];
                v2 = make_float2(wv, usplit(wv).x);   // {w, ~w/f2}
            }
            sw[0][tid] = v2;
        }
#pragma unroll
        for (int kk = 0; kk < 6; ++kk) {
            int idx = tid + kk * NTHR;
            if (idx < CELLS) {
                int r = idx >> 6, q = idx & 63;
                int iy = h0 + r - PAD_, ix = q - PAD_;
                float v = 0.0f;
                if ((unsigned)iy < H_ && (unsigned)ix < W_) v = xp[iy * W_ + ix];
                sm[0][idx] = usplit(v);
            }
        }
    }
    __syncthreads();

    // ---- persistent tile loop ----
    for (int k = t0; k < t1; ++k) {
        const int buf = (k - t0) & 1;
        const int plane = k >> 1;
        const int h0 = (k & 1) * HR;
        const bool more = (k + 1 < t1);

        // stage A: issue next tile's global loads (6 independent LDGs)
        float v[6];
        int nplane = 0;
        if (more) {
            const int nt = k + 1;
            nplane = nt >> 1;
            const int nh0 = (nt & 1) * HR;
            const float* __restrict__ xp = x + (size_t)nplane * (H_ * W_);
#pragma unroll
            for (int kk = 0; kk < 6; ++kk) {
                int idx = tid + kk * NTHR;
                float vv = 0.0f;
                if (idx < CELLS) {
                    int r = idx >> 6, q = idx & 63;
                    int iy = nh0 + r - PAD_, ix = q - PAD_;
                    if ((unsigned)iy < H_ && (unsigned)ix < W_)
                        vv = __ldg(xp + iy * W_ + ix);
                }
                v[kk] = vv;
            }
        }

        // stage B: compute current tile from sm[buf]
        {
            const ulonglong2* __restrict__ swq = (const ulonglong2*)sw[buf];
            const float2* __restrict__ smb = sm[buf];
            unsigned long long acc00 = 0ull, acc01 = 0ull,
                               acc10 = 0ull, acc11 = 0ull;
#pragma unroll
            for (int t = 0; t < 8; ++t) {
                const unsigned long long* pr =
                    (const unsigned long long*)&smb[((y0 + t) << 6) + x0];
                unsigned long long p[8];
                ((ulonglong2*)p)[0] = ((const ulonglong2*)pr)[0];
                ((ulonglong2*)p)[1] = ((const ulonglong2*)pr)[1];
                ((ulonglong2*)p)[2] = ((const ulonglong2*)pr)[2];
                ((ulonglong2*)p)[3] = ((const ulonglong2*)pr)[3];

                // oy = 0 uses kernel row i = t (valid t<=6)
                if (t <= 6) {
#pragma unroll
                    for (int jj = 0; jj < 4; ++jj) {       // j = 2jj, 2jj+1
                        ulonglong2 wp = swq[(t << 2) + jj]; // LDS.128 bcast
                        const int j0 = 2 * jj;
                        acc00 = fma2(p[j0],     wp.x, acc00);
                        acc01 = fma2(p[j0 + 1], wp.x, acc01);
                        if (j0 + 1 < K_) {
                            acc00 = fma2(p[j0 + 1], wp.y, acc00);
                            acc01 = fma2(p[j0 + 2], wp.y, acc01);
                        }
                    }
                }
                // oy = 1 uses kernel row i = t-1 (valid t>=1)
                if (t >= 1) {
#pragma unroll
                    for (int jj = 0; jj < 4; ++jj) {
                        ulonglong2 wp = swq[((t - 1) << 2) + jj];
                        const int j0 = 2 * jj;
                        acc10 = fma2(p[j0],     wp.x, acc10);
                        acc11 = fma2(p[j0 + 1], wp.x, acc11);
                        if (j0 + 1 < K_) {
                            acc10 = fma2(p[j0 + 1], wp.y, acc10);
                            acc11 = fma2(p[j0 + 2], wp.y, acc11);
                        }
                    }
                }
            }
            float* op = out + (size_t)plane * (H_ * W_) + (h0 + y0) * W_ + x0;
            *(float2*)(op)      = make_float2(pairsum(acc00), pairsum(acc01));
            *(float2*)(op + W_) = make_float2(pairsum(acc10), pairsum(acc11));
        }

        // stage C: split staged regs into sm[buf^1], next weights
        if (more) {
            if (tid < K_ * 8) {
                int j = tid & 7;
                float2 v2 = make_float2(0.0f, 0.0f);
                if (j < K_) {
                    float wv = w[(nplane % C_) * (K_ * K_) + (tid >> 3) * K_ + j];
                    v2 = make_float2(wv, usplit(wv).x);
                }
                sw[buf ^ 1][tid] = v2;
            }
#pragma unroll
            for (int kk = 0; kk < 6; ++kk) {
                int idx = tid + kk * NTHR;
                if (idx < CELLS) sm[buf ^ 1][idx] = usplit(v[kk]);
            }
        }
        __syncthreads();
    }
}

extern "C" void kernel_launch(void* const* d_in, const int* in_sizes, int n_in,
                              void* d_out, int out_size) {
    const float* x  = (const float*)d_in[0];   // (4,192,56,56) f32
    const float* wt = (const float*)d_in[1];   // (192,1,7,7)  f32
    float* out = (float*)d_out;                // (4,192,56,56) f32
    (void)in_sizes; (void)n_in; (void)out_size;
    waconv_kernel<<<NBLK, NTHR>>>(x, wt, out);
}

// round 13
// speedup vs baseline: 1.1889x; 1.1889x over previous
#include <cuda_runtime.h>

// Appro_WAConv2d: depthwise 7x7 conv with mantissa-approximation factor.
//   term = x*w*(f1+f2-1)/(f1*f2) = u*w + s*(w/f2),  u = x/f1, s = x - u
// Packed f32x2: smem {u,s} float2, weights {w, w/f2}; one fma.rn.f32x2/tap.
// Round-13: R10 skeleton (half-plane persistent tiles, double-buffered
// A/B/C pipeline, occ-3) +
//  (a) division-free mantissa split (validated R11/R12): u = x/f1 is a
//      signed power of two up to O(1e-7); integer ops, no MUFU.RCP.
//  (b) weight-row register rotation in stage B: oy=1 at iter t reuses the
//      row loaded for oy=0 at iter t-1 (2-row rotating window, 16 regs)
//      -> weight LDS.128 per thread-tile 56 -> 28, L1 wavefronts -14%.
// Lesson from R5/R8/R12: reg caps below ~48 destroy ILP; stay at occ-3.

#define B_   4
#define C_   192
#define H_   56
#define W_   56
#define K_   7
#define PAD_ 3
#define HR    28            // output rows per tile (half plane)
#define SMROWS 34           // 28 + 2*3 halo rows
#define SR    64            // smem row stride in float2 (pow2 indexing)
#define NTHR  392
#define CELLS (SMROWS * SR) // 2176
#define NTILES (B_ * C_ * 2)  // 1536
#define NBLK  456           // 152 SMs * 3 resident blocks

// division-free split: u ~= v/f1 (signed power of 2), s = v - u.
// f1 = mantissa-map(|v|+eps) shares the mantissa of a=|v|+eps, so a/f1 is
// exactly 2^(exp(a) + topbit); dropped eps-scale term is O(1e-7).
__device__ __forceinline__ float2 usplit(float v) {
    float a = fabsf(v) + 1e-7f;
    unsigned ab = __float_as_uint(a);
    unsigned ub = (__float_as_uint(v) & 0x80000000u)
                | ((ab & 0x7F800000u) + ((ab & 0x00400000u) << 1));
    float u = __uint_as_float(ub);
    return make_float2(u, v - u);
}

__device__ __forceinline__ unsigned long long fma2(unsigned long long a,
                                                   unsigned long long b,
                                                   unsigned long long c) {
    unsigned long long d;
    asm("fma.rn.f32x2 %0, %1, %2, %3;" : "=l"(d) : "l"(a), "l"(b), "l"(c));
    return d;
}

__device__ __forceinline__ float pairsum(unsigned long long v) {
    return __uint_as_float((unsigned)v) + __uint_as_float((unsigned)(v >> 32));
}

__global__ __launch_bounds__(NTHR, 3)
void waconv_kernel(const float* __restrict__ x,
                   const float* __restrict__ w,
                   float* __restrict__ out) {
    __shared__ __align__(16) float2 sm[2][CELLS];     // {u, s} interleaved
    __shared__ __align__(16) float2 sw[2][K_ * 8];    // {w, w/f2}, rows of 8

    const int tid = threadIdx.x;
    const int t0 = (int)(((long long)blockIdx.x       * NTILES) / NBLK);
    const int t1 = (int)(((long long)(blockIdx.x + 1) * NTILES) / NBLK);

    const int ty = tid / 28;               // 0..13
    const int tx = tid - ty * 28;          // 0..27
    const int y0 = ty * 2;
    const int x0 = tx * 2;

    // ---- prologue: fill buffer 0 with tile t0 (direct, stalls once) ----
    {
        const int plane = t0 >> 1;
        const int h0 = (t0 & 1) * HR;
        const float* __restrict__ xp = x + (size_t)plane * (H_ * W_);
        if (tid < K_ * 8) {
            int j = tid & 7;
            float2 v2 = make_float2(0.0f, 0.0f);
            if (j < K_) {
                float wv = w[(plane % C_) * (K_ * K_) + (tid >> 3) * K_ + j];
                v2 = make_float2(wv, usplit(wv).x);   // {w, ~w/f2}
            }
            sw[0][tid] = v2;
        }
#pragma unroll
        for (int kk = 0; kk < 6; ++kk) {
            int idx = tid + kk * NTHR;
            if (idx < CELLS) {
                int r = idx >> 6, q = idx & 63;
                int iy = h0 + r - PAD_, ix = q - PAD_;
                float v = 0.0f;
                if ((unsigned)iy < H_ && (unsigned)ix < W_) v = xp[iy * W_ + ix];
                sm[0][idx] = usplit(v);
            }
        }
    }
    __syncthreads();

    // ---- persistent tile loop ----
    for (int k = t0; k < t1; ++k) {
        const int buf = (k - t0) & 1;
        const int plane = k >> 1;
        const int h0 = (k & 1) * HR;
        const bool more = (k + 1 < t1);

        // stage A: issue next tile's global loads (6 independent LDGs)
        float v[6];
        int nplane = 0;
        if (more) {
            const int nt = k + 1;
            nplane = nt >> 1;
            const int nh0 = (nt & 1) * HR;
            const float* __restrict__ xp = x + (size_t)nplane * (H_ * W_);
#pragma unroll
            for (int kk = 0; kk < 6; ++kk) {
                int idx = tid + kk * NTHR;
                float vv = 0.0f;
                if (idx < CELLS) {
                    int r = idx >> 6, q = idx & 63;
                    int iy = nh0 + r - PAD_, ix = q - PAD_;
                    if ((unsigned)iy < H_ && (unsigned)ix < W_)
                        vv = __ldg(xp + iy * W_ + ix);
                }
                v[kk] = vv;
            }
        }

        // stage B: compute current tile from sm[buf]
        {
            const ulonglong2* __restrict__ swq = (const ulonglong2*)sw[buf];
            const float2* __restrict__ smb = sm[buf];
            unsigned long long acc00 = 0ull, acc01 = 0ull,
                               acc10 = 0ull, acc11 = 0ull;
            ulonglong2 wcur[4], wprev[4];
#pragma unroll
            for (int t = 0; t < 8; ++t) {
                const unsigned long long* pr =
                    (const unsigned long long*)&smb[((y0 + t) << 6) + x0];
                unsigned long long p[8];
                ((ulonglong2*)p)[0] = ((const ulonglong2*)pr)[0];
                ((ulonglong2*)p)[1] = ((const ulonglong2*)pr)[1];
                ((ulonglong2*)p)[2] = ((const ulonglong2*)pr)[2];
                ((ulonglong2*)p)[3] = ((const ulonglong2*)pr)[3];

                // load weight row t once; oy=1 at t+1 reuses it as wprev
                if (t <= 6) {
#pragma unroll
                    for (int jj = 0; jj < 4; ++jj)
                        wcur[jj] = swq[(t << 2) + jj];     // LDS.128 bcast
                }

                // oy = 0 uses kernel row i = t (valid t<=6)
                if (t <= 6) {
#pragma unroll
                    for (int jj = 0; jj < 4; ++jj) {       // j = 2jj, 2jj+1
                        const int j0 = 2 * jj;
                        acc00 = fma2(p[j0],     wcur[jj].x, acc00);
                        acc01 = fma2(p[j0 + 1], wcur[jj].x, acc01);
                        if (j0 + 1 < K_) {
                            acc00 = fma2(p[j0 + 1], wcur[jj].y, acc00);
                            acc01 = fma2(p[j0 + 2], wcur[jj].y, acc01);
                        }
                    }
                }
                // oy = 1 uses kernel row i = t-1 (valid t>=1)
                if (t >= 1) {
#pragma unroll
                    for (int jj = 0; jj < 4; ++jj) {
                        const int j0 = 2 * jj;
                        acc10 = fma2(p[j0],     wprev[jj].x, acc10);
                        acc11 = fma2(p[j0 + 1], wprev[jj].x, acc11);
                        if (j0 + 1 < K_) {
                            acc10 = fma2(p[j0 + 1], wprev[jj].y, acc10);
                            acc11 = fma2(p[j0 + 2], wprev[jj].y, acc11);
                        }
                    }
                }
                // rotate window (register renaming after unroll, no real MOVs)
#pragma unroll
                for (int jj = 0; jj < 4; ++jj) wprev[jj] = wcur[jj];
            }
            float* op = out + (size_t)plane * (H_ * W_) + (h0 + y0) * W_ + x0;
            *(float2*)(op)      = make_float2(pairsum(acc00), pairsum(acc01));
            *(float2*)(op + W_) = make_float2(pairsum(acc10), pairsum(acc11));
        }

        // stage C: split staged regs into sm[buf^1], next weights
        if (more) {
            if (tid < K_ * 8) {
                int j = tid & 7;
                float2 v2 = make_float2(0.0f, 0.0f);
                if (j < K_) {
                    float wv = w[(nplane % C_) * (K_ * K_) + (tid >> 3) * K_ + j];
                    v2 = make_float2(wv, usplit(wv).x);
                }
                sw[buf ^ 1][tid] = v2;
            }
#pragma unroll
            for (int kk = 0; kk < 6; ++kk) {
                int idx = tid + kk * NTHR;
                if (idx < CELLS) sm[buf ^ 1][idx] = usplit(v[kk]);
            }
        }
        __syncthreads();
    }
}

extern "C" void kernel_launch(void* const* d_in, const int* in_sizes, int n_in,
                              void* d_out, int out_size) {
    const float* x  = (const float*)d_in[0];   // (4,192,56,56) f32
    const float* wt = (const float*)d_in[1];   // (192,1,7,7)  f32
    float* out = (float*)d_out;                // (4,192,56,56) f32
    (void)in_sizes; (void)n_in; (void)out_size;
    waconv_kernel<<<NBLK, NTHR>>>(x, wt, out);
}